// round 15
// baseline (speedup 1.0000x reference)
#include <cuda_runtime.h>

// Problem constants
#define Vv 50000
#define Ee 128
#define Hh 64
#define Gg 256   // 4*H
#define Bb 512
#define Ss 512

// 51.2 MB scratch: projTable[v][g] = emb[v] @ Wih0^T + (bih0+bhh0)
__device__ float g_projT[Vv * (size_t)Gg];
__device__ int g_is64;

typedef unsigned long long ull;

__device__ __forceinline__ ull ffma2(ull a, ull b, ull acc) {
    ull d;
    asm("fma.rn.f32x2 %0, %1, %2, %3;" : "=l"(d) : "l"(a), "l"(b), "l"(acc));
    return d;
}
__device__ __forceinline__ ull pack2(float lo, float hi) {
    return ((ull)__float_as_uint(hi) << 32) | (ull)__float_as_uint(lo);
}
__device__ __forceinline__ float hsum2(ull a) {
    return __uint_as_float((unsigned int)a) + __uint_as_float((unsigned int)(a >> 32));
}
__device__ __forceinline__ float sigmf(float x) {
    return __fdividef(1.0f, 1.0f + __expf(-x));
}
__device__ __forceinline__ float tanhfast(float x) {
    // 1 - 2/(e^{2x}+1); saturates correctly at +-1 via MUFU rcp(inf)=0 / exp(-big)=0
    float e = __expf(2.0f * x);
    return 1.0f - __fdividef(2.0f, e + 1.0f);
}

// ---------------------------------------------------------------------------
// Phase A: projTable[V,256] = emb[V,128] @ Wih0^T[128,256] + (bih0+bhh0)
// Also performs int64-vs-int32 sniffing of input_seq (block 0, thread 0).
// E loads now 128-bit (was 64-bit broadcast) -> ~half the LDS issues.
// ---------------------------------------------------------------------------
__global__ void __launch_bounds__(256, 1)
proj_kernel(const float* __restrict__ emb, const float* __restrict__ Wih0,
            const float* __restrict__ bih0, const float* __restrict__ bhh0,
            const void* __restrict__ seq_raw) {
    extern __shared__ ull sm[];
    ull* Wsm = sm;               // [64 k2][256 g]
    ull* Esm = sm + 64 * 256;    // [64 k2][32 r]

    const int tid = threadIdx.x;
    const int v0 = blockIdx.x * 32;

    if (blockIdx.x == 0 && tid == 0) {
        // int64 little-endian values < 2^31 have all-zero high words
        const unsigned int* wd = (const unsigned int*)seq_raw;
        int is64 = 1;
        for (int i = 0; i < 128; ++i)
            if (wd[2 * i + 1] != 0u) { is64 = 0; break; }
        g_is64 = is64;
    }

    // Load Wih0: global [g][e] row-major -> smem [k2][g] as (e=2k2, 2k2+1) pair
    for (int i = tid; i < 256 * 64; i += 256) {
        int gg = i >> 6, k2 = i & 63;
        float2 w = *reinterpret_cast<const float2*>(Wih0 + (size_t)gg * Ee + 2 * k2);
        Wsm[k2 * 256 + gg] = pack2(w.x, w.y);
    }
    // Load 32 emb rows -> smem [k2][r]
    for (int i = tid; i < 32 * 64; i += 256) {
        int r = i >> 6, k2 = i & 63;
        int v = v0 + r;
        float2 e = make_float2(0.f, 0.f);
        if (v < Vv) e = *reinterpret_cast<const float2*>(emb + (size_t)v * Ee + 2 * k2);
        Esm[k2 * 32 + r] = pack2(e.x, e.y);
    }
    __syncthreads();

    const int gg = tid;  // output column
    ull acc[32];
#pragma unroll
    for (int r = 0; r < 32; ++r) acc[r] = 0ull;

#pragma unroll 2
    for (int k2 = 0; k2 < 64; ++k2) {
        ull w = Wsm[k2 * 256 + gg];
        const ulonglong2* ep2 = (const ulonglong2*)&Esm[k2 * 32];
#pragma unroll
        for (int r2 = 0; r2 < 16; ++r2) {
            ulonglong2 e = ep2[r2];
            acc[2 * r2]     = ffma2(e.x, w, acc[2 * r2]);
            acc[2 * r2 + 1] = ffma2(e.y, w, acc[2 * r2 + 1]);
        }
    }

    float b0 = bih0[gg] + bhh0[gg];
#pragma unroll
    for (int r = 0; r < 32; ++r) {
        int v = v0 + r;
        if (v < Vv) g_projT[(size_t)v * Gg + gg] = hsum2(acc[r]) + b0;
    }
}

// ---------------------------------------------------------------------------
// Phase B: fused 2-layer LSTM recurrence + final FC, software-pipelined.
// 128 CTAs x 4 batch rows, 256 threads.
//   * each phase computes [layer1(t) + layer0(t+1)] together: both read h0[t],
//     so one set of h0 broadcast loads feeds three weight streams, and the
//     whole phase ends in ONE __syncthreads (was 2 barriers per step).
//   * layer-1 weights in registers (128 regs/thr); Whh0 in smem.
//   * h0/h1 double-buffered by phase parity (row stride 72, conflict-free).
//   * gate exchange per warp, stride 20 -> conflict-free scalar reads.
// ---------------------------------------------------------------------------
__global__ void __launch_bounds__(256, 1)
lstm_kernel(const void* __restrict__ seq_raw,
            const float* __restrict__ Whh0g, const float* __restrict__ Wih1g,
            const float* __restrict__ Whh1g,
            const float* __restrict__ bih1, const float* __restrict__ bhh1,
            const float* __restrict__ Wfc, const float* __restrict__ bfc,
            float* __restrict__ out) {
    extern __shared__ __align__(16) char smraw[];
    ulonglong2* W0v = (ulonglong2*)smraw;   // Whh0 [16 k4][256 g]  (64 KB)
    float* h0f = (float*)(W0v + 16 * 256);  // [2 buf][4 r][72]
    float* h1f = h0f + 576;                 // [2 buf][4 r][72]
    float* gts = h1f + 576;                 // [8 warp][2 set][8 j][stride 20]
    int*   idxs = (int*)(gts + 2560);       // [4 r][512 t]

    const int tid = threadIdx.x;
    const int brow0 = blockIdx.x * 4;

    const int lane = tid & 31;
    const int w    = tid >> 5;
    const int qq   = lane >> 3;        // gate quarter (i,f,g,o)
    const int jl   = lane & 7;
    const int g    = qq * 64 + w * 8 + jl;   // GEMV gate column
    const int ar   = qq;               // activation role: batch row
    const int aj   = w * 8 + jl;       // activation role: hidden unit

    // Repack Whh0 ([256 g][64 k] row-major global) -> smem [k4][g] ulonglong2.
    for (int i = tid; i < 16 * 256; i += 256) {
        int gg = i >> 4, k4 = i & 15;
        float4 w0 = *(const float4*)(Whh0g + (size_t)gg * Hh + k4 * 4);
        W0v[k4 * 256 + gg] = make_ulonglong2(pack2(w0.x, w0.y), pack2(w0.z, w0.w));
    }
    // Layer-1 weights for this thread's gate column -> registers (64 ull).
    ull wa[32], wb[32];
#pragma unroll
    for (int k2 = 0; k2 < 32; ++k2) {
        float2 a = *(const float2*)(Wih1g + (size_t)g * Hh + 2 * k2);
        float2 b = *(const float2*)(Whh1g + (size_t)g * Hh + 2 * k2);
        wa[k2] = pack2(a.x, a.y);
        wb[k2] = pack2(b.x, b.y);
    }
    // Indices for this CTA's 4 batch rows (dtype-adaptive)
    const int is64 = g_is64;
    for (int i = tid; i < 4 * Ss; i += 256) {
        int r = i >> 9, t = i & (Ss - 1);
        long long v;
        if (is64) v = ((const long long*)seq_raw)[(size_t)(brow0 + r) * Ss + t];
        else      v = (long long)((const int*)seq_raw)[(size_t)(brow0 + r) * Ss + t];
        idxs[r * Ss + t] = (int)v;
    }
    for (int i = tid; i < 1152; i += 256) h0f[i] = 0.f;  // zeros h0f+h1f (contiguous)
    const float bb = bih1[g] + bhh1[g];
    __syncthreads();

    float* gw1 = gts + w * 320;        // layer-1 gate exchange (160 floats)
    float* gw0 = gw1 + 160;            // layer-0(t+1) gate exchange
    const float* pT = g_projT;
    float c0 = 0.f, c1 = 0.f;

    // ---- prologue: layer-0 at t=0 has h0=0 -> gates are just the projections
    {
        float4 v;
        v.x = pT[(size_t)idxs[0 * Ss + 0] * Gg + g];
        v.y = pT[(size_t)idxs[1 * Ss + 0] * Gg + g];
        v.z = pT[(size_t)idxs[2 * Ss + 0] * Gg + g];
        v.w = pT[(size_t)idxs[3 * Ss + 0] * Gg + g];
        *(float4*)(gw0 + jl * 20 + qq * 4) = v;
        __syncwarp();
        float gi = gw0[jl * 20 + 0  + ar];
        float gf = gw0[jl * 20 + 4  + ar];
        float gG = gw0[jl * 20 + 8  + ar];
        float go = gw0[jl * 20 + 12 + ar];
        float iv = sigmf(gi), fv = sigmf(gf);
        float gv = tanhfast(gG), ov = sigmf(go);
        c0 = fv * c0 + iv * gv;
        h0f[/*buf0*/ ar * 72 + aj] = ov * tanhfast(c0);
        __syncthreads();  // h0[0] visible to all warps
    }

    // ---- main phases: ph handles layer1(t=ph) + layer0(t=ph+1), ONE barrier
#pragma unroll 1
    for (int ph = 0; ph < Ss - 1; ++ph) {
        const int p = ph & 1;
        const ulonglong2* yv = (const ulonglong2*)(h0f + p * 288);        // h0[ph]
        const ulonglong2* zv = (const ulonglong2*)(h1f + (p ^ 1) * 288);  // h1[ph-1]
        float* h0wr = h0f + (p ^ 1) * 288;  // h0[ph+1]
        float* h1wr = h1f + p * 288;        // h1[ph]

        // layer-0(ph+1) input projections from L2-resident table (early issue)
        float xv0 = pT[(size_t)idxs[0 * Ss + ph + 1] * Gg + g];
        float xv1 = pT[(size_t)idxs[1 * Ss + ph + 1] * Gg + g];
        float xv2 = pT[(size_t)idxs[2 * Ss + ph + 1] * Gg + g];
        float xv3 = pT[(size_t)idxs[3 * Ss + ph + 1] * Gg + g];

        // combined GEMV: a = y@Whh0^T (next layer-0), d = y@Wih1^T + z@Whh1^T
        ull a0 = 0, a1 = 0, a2 = 0, a3 = 0;
        ull d0 = 0, d1 = 0, d2 = 0, d3 = 0;
#pragma unroll 4
        for (int k4 = 0; k4 < 16; ++k4) {
            ulonglong2 wv = W0v[k4 * 256 + g];
            ulonglong2 yA = yv[k4];
            ulonglong2 yB = yv[18 + k4];
            ulonglong2 yC = yv[36 + k4];
            ulonglong2 yD = yv[54 + k4];
            ulonglong2 zA = zv[k4];
            ulonglong2 zB = zv[18 + k4];
            ulonglong2 zC = zv[36 + k4];
            ulonglong2 zD = zv[54 + k4];
            a0 = ffma2(yA.x, wv.x, a0); a0 = ffma2(yA.y, wv.y, a0);
            a1 = ffma2(yB.x, wv.x, a1); a1 = ffma2(yB.y, wv.y, a1);
            a2 = ffma2(yC.x, wv.x, a2); a2 = ffma2(yC.y, wv.y, a2);
            a3 = ffma2(yD.x, wv.x, a3); a3 = ffma2(yD.y, wv.y, a3);
            d0 = ffma2(yA.x, wa[2 * k4], d0); d0 = ffma2(yA.y, wa[2 * k4 + 1], d0);
            d0 = ffma2(zA.x, wb[2 * k4], d0); d0 = ffma2(zA.y, wb[2 * k4 + 1], d0);
            d1 = ffma2(yB.x, wa[2 * k4], d1); d1 = ffma2(yB.y, wa[2 * k4 + 1], d1);
            d1 = ffma2(zB.x, wb[2 * k4], d1); d1 = ffma2(zB.y, wb[2 * k4 + 1], d1);
            d2 = ffma2(yC.x, wa[2 * k4], d2); d2 = ffma2(yC.y, wa[2 * k4 + 1], d2);
            d2 = ffma2(zC.x, wb[2 * k4], d2); d2 = ffma2(zC.y, wb[2 * k4 + 1], d2);
            d3 = ffma2(yD.x, wa[2 * k4], d3); d3 = ffma2(yD.y, wa[2 * k4 + 1], d3);
            d3 = ffma2(zD.x, wb[2 * k4], d3); d3 = ffma2(zD.y, wb[2 * k4 + 1], d3);
        }
        {
            float4 v1, v0n;
            v1.x = hsum2(d0) + bb;  v0n.x = hsum2(a0) + xv0;
            v1.y = hsum2(d1) + bb;  v0n.y = hsum2(a1) + xv1;
            v1.z = hsum2(d2) + bb;  v0n.z = hsum2(a2) + xv2;
            v1.w = hsum2(d3) + bb;  v0n.w = hsum2(a3) + xv3;
            *(float4*)(gw1 + jl * 20 + qq * 4) = v1;
            *(float4*)(gw0 + jl * 20 + qq * 4) = v0n;
        }
        __syncwarp();
        {   // act1(t=ph)
            float gi = gw1[jl * 20 + 0  + ar];
            float gf = gw1[jl * 20 + 4  + ar];
            float gG = gw1[jl * 20 + 8  + ar];
            float go = gw1[jl * 20 + 12 + ar];
            float iv = sigmf(gi), fv = sigmf(gf);
            float gv = tanhfast(gG), ov = sigmf(go);
            c1 = fv * c1 + iv * gv;
            h1wr[ar * 72 + aj] = ov * tanhfast(c1);
        }
        {   // act0(t=ph+1)
            float gi = gw0[jl * 20 + 0  + ar];
            float gf = gw0[jl * 20 + 4  + ar];
            float gG = gw0[jl * 20 + 8  + ar];
            float go = gw0[jl * 20 + 12 + ar];
            float iv = sigmf(gi), fv = sigmf(gf);
            float gv = tanhfast(gG), ov = sigmf(go);
            c0 = fv * c0 + iv * gv;
            h0wr[ar * 72 + aj] = ov * tanhfast(c0);
        }
        __syncthreads();  // single barrier per phase
    }

    // ---- epilogue: layer-1 at t = Ss-1 = 511
    {
        const int p = (Ss - 1) & 1;  // 1
        const ulonglong2* yv = (const ulonglong2*)(h0f + p * 288);        // h0[511]
        const ulonglong2* zv = (const ulonglong2*)(h1f + (p ^ 1) * 288);  // h1[510]
        ull d0 = 0, d1 = 0, d2 = 0, d3 = 0;
#pragma unroll 4
        for (int k4 = 0; k4 < 16; ++k4) {
            ulonglong2 yA = yv[k4],      yB = yv[18 + k4];
            ulonglong2 yC = yv[36 + k4], yD = yv[54 + k4];
            ulonglong2 zA = zv[k4],      zB = zv[18 + k4];
            ulonglong2 zC = zv[36 + k4], zD = zv[54 + k4];
            d0 = ffma2(yA.x, wa[2 * k4], d0); d0 = ffma2(yA.y, wa[2 * k4 + 1], d0);
            d0 = ffma2(zA.x, wb[2 * k4], d0); d0 = ffma2(zA.y, wb[2 * k4 + 1], d0);
            d1 = ffma2(yB.x, wa[2 * k4], d1); d1 = ffma2(yB.y, wa[2 * k4 + 1], d1);
            d1 = ffma2(zB.x, wb[2 * k4], d1); d1 = ffma2(zB.y, wb[2 * k4 + 1], d1);
            d2 = ffma2(yC.x, wa[2 * k4], d2); d2 = ffma2(yC.y, wa[2 * k4 + 1], d2);
            d2 = ffma2(zC.x, wb[2 * k4], d2); d2 = ffma2(zC.y, wb[2 * k4 + 1], d2);
            d3 = ffma2(yD.x, wa[2 * k4], d3); d3 = ffma2(yD.y, wa[2 * k4 + 1], d3);
            d3 = ffma2(zD.x, wb[2 * k4], d3); d3 = ffma2(zD.y, wb[2 * k4 + 1], d3);
        }
        {
            float4 v1;
            v1.x = hsum2(d0) + bb;
            v1.y = hsum2(d1) + bb;
            v1.z = hsum2(d2) + bb;
            v1.w = hsum2(d3) + bb;
            *(float4*)(gw1 + jl * 20 + qq * 4) = v1;
        }
        __syncwarp();
        {
            float gi = gw1[jl * 20 + 0  + ar];
            float gf = gw1[jl * 20 + 4  + ar];
            float gG = gw1[jl * 20 + 8  + ar];
            float go = gw1[jl * 20 + 12 + ar];
            float iv = sigmf(gi), fv = sigmf(gf);
            float gv = tanhfast(gG), ov = sigmf(go);
            c1 = fv * c1 + iv * gv;
            h1f[p * 288 + ar * 72 + aj] = ov * tanhfast(c1);  // h1[511] -> buf1
        }
        __syncthreads();
    }

    // ---- final FC: out = sigmoid(h1_T @ Wfc^T + bfc), shape [B, 2] ----
    if (tid < 8) {
        const float* hfin = h1f + ((Ss - 1) & 1) * 288;
        int r = tid >> 1, o = tid & 1;
        float s = bfc[o];
#pragma unroll
        for (int j = 0; j < 64; ++j) s += hfin[r * 72 + j] * Wfc[o * 64 + j];
        out[(size_t)(brow0 + r) * 2 + o] = sigmf(s);
    }
}

// ---------------------------------------------------------------------------
extern "C" void kernel_launch(void* const* d_in, const int* in_sizes, int n_in,
                              void* d_out, int out_size) {
    const void*  seq  = d_in[0];
    const float* emb  = (const float*)d_in[1];
    const float* Wih0 = (const float*)d_in[2];
    const float* Whh0 = (const float*)d_in[3];
    const float* bih0 = (const float*)d_in[4];
    const float* bhh0 = (const float*)d_in[5];
    const float* Wih1 = (const float*)d_in[6];
    const float* Whh1 = (const float*)d_in[7];
    const float* bih1 = (const float*)d_in[8];
    const float* bhh1 = (const float*)d_in[9];
    const float* Wfc  = (const float*)d_in[10];
    const float* bfc  = (const float*)d_in[11];
    float* out = (float*)d_out;

    const int projSmem = (64 * 256 + 64 * 32) * 8;                           // 147456
    const int lstmSmem = 16 * 256 * 16 + (576 + 576 + 2560) * 4 + 4 * Ss * 4;  // 88576

    cudaFuncSetAttribute(proj_kernel, cudaFuncAttributeMaxDynamicSharedMemorySize, projSmem);
    cudaFuncSetAttribute(lstm_kernel, cudaFuncAttributeMaxDynamicSharedMemorySize, lstmSmem);

    proj_kernel<<<(Vv + 31) / 32, 256, projSmem>>>(emb, Wih0, bih0, bhh0, seq);
    lstm_kernel<<<Bb / 4, 256, lstmSmem>>>(seq, Whh0, Wih1, Whh1,
                                           bih1, bhh1, Wfc, bfc, out);
}

// round 17
// speedup vs baseline: 1.3457x; 1.3457x over previous
#include <cuda_runtime.h>

// Problem constants
#define Vv 50000
#define Ee 128
#define Hh 64
#define Gg 256   // 4*H
#define Bb 512
#define Ss 512

// 51.2 MB scratch: projTable[v][g] = emb[v] @ Wih0^T + (bih0+bhh0)
__device__ float g_projT[Vv * (size_t)Gg];
__device__ int g_is64;

typedef unsigned long long ull;

__device__ __forceinline__ ull ffma2(ull a, ull b, ull acc) {
    ull d;
    asm("fma.rn.f32x2 %0, %1, %2, %3;" : "=l"(d) : "l"(a), "l"(b), "l"(acc));
    return d;
}
__device__ __forceinline__ ull pack2(float lo, float hi) {
    return ((ull)__float_as_uint(hi) << 32) | (ull)__float_as_uint(lo);
}
__device__ __forceinline__ float hsum2(ull a) {
    return __uint_as_float((unsigned int)a) + __uint_as_float((unsigned int)(a >> 32));
}
__device__ __forceinline__ float sigmf(float x) {
    return __fdividef(1.0f, 1.0f + __expf(-x));
}
__device__ __forceinline__ float tanhfast(float x) {
    // 1 - 2/(e^{2x}+1); saturates correctly at +-1 via MUFU rcp(inf)=0 / exp(-big)=0
    float e = __expf(2.0f * x);
    return 1.0f - __fdividef(2.0f, e + 1.0f);
}

// ---------------------------------------------------------------------------
// Phase A: projTable[V,256] = emb[V,128] @ Wih0^T[128,256] + (bih0+bhh0)
// Also performs int64-vs-int32 sniffing of input_seq (block 0, thread 0).
// ---------------------------------------------------------------------------
__global__ void __launch_bounds__(256, 1)
proj_kernel(const float* __restrict__ emb, const float* __restrict__ Wih0,
            const float* __restrict__ bih0, const float* __restrict__ bhh0,
            const void* __restrict__ seq_raw) {
    extern __shared__ ull sm[];
    ull* Wsm = sm;               // [64 k2][256 g]
    ull* Esm = sm + 64 * 256;    // [64 k2][32 r]

    const int tid = threadIdx.x;
    const int v0 = blockIdx.x * 32;

    if (blockIdx.x == 0 && tid == 0) {
        // int64 little-endian values < 2^31 have all-zero high words
        const unsigned int* wd = (const unsigned int*)seq_raw;
        int is64 = 1;
        for (int i = 0; i < 128; ++i)
            if (wd[2 * i + 1] != 0u) { is64 = 0; break; }
        g_is64 = is64;
    }

    // Load Wih0: global [g][e] row-major -> smem [k2][g] as (e=2k2, 2k2+1) pair
    for (int i = tid; i < 256 * 64; i += 256) {
        int gg = i >> 6, k2 = i & 63;
        float2 w = *reinterpret_cast<const float2*>(Wih0 + (size_t)gg * Ee + 2 * k2);
        Wsm[k2 * 256 + gg] = pack2(w.x, w.y);
    }
    // Load 32 emb rows -> smem [k2][r]
    for (int i = tid; i < 32 * 64; i += 256) {
        int r = i >> 6, k2 = i & 63;
        int v = v0 + r;
        float2 e = make_float2(0.f, 0.f);
        if (v < Vv) e = *reinterpret_cast<const float2*>(emb + (size_t)v * Ee + 2 * k2);
        Esm[k2 * 32 + r] = pack2(e.x, e.y);
    }
    __syncthreads();

    const int gg = tid;  // output column
    ull acc[32];
#pragma unroll
    for (int r = 0; r < 32; ++r) acc[r] = 0ull;

#pragma unroll 2
    for (int k2 = 0; k2 < 64; ++k2) {
        ull w = Wsm[k2 * 256 + gg];
        const ulonglong2* ep2 = (const ulonglong2*)&Esm[k2 * 32];
#pragma unroll
        for (int r2 = 0; r2 < 16; ++r2) {
            ulonglong2 e = ep2[r2];
            acc[2 * r2]     = ffma2(e.x, w, acc[2 * r2]);
            acc[2 * r2 + 1] = ffma2(e.y, w, acc[2 * r2 + 1]);
        }
    }

    float b0 = bih0[gg] + bhh0[gg];
#pragma unroll
    for (int r = 0; r < 32; ++r) {
        int v = v0 + r;
        if (v < Vv) g_projT[(size_t)v * Gg + gg] = hsum2(acc[r]) + b0;
    }
}

// ---------------------------------------------------------------------------
// Phase B: fused 2-layer LSTM recurrence + final FC, software-pipelined.
// 128 CTAs x 4 batch rows, 256 threads.
//   * each phase computes [layer1(t) + layer0(t+1)] together: both read h0[t],
//     so one set of h0 broadcast loads feeds three weight streams, and the
//     whole phase ends in ONE __syncthreads.
//   * layer-1 weights in REGISTERS. The combined GEMV loop MUST be fully
//     unrolled: any runtime indexing of wa[]/wb[] demotes them to local
//     memory (this was the round-15 regression: regs 242->142 + LDL traffic).
//   * h0/h1 double-buffered by phase parity (row stride 72, conflict-free).
//   * gate exchange per warp, stride 20 -> conflict-free scalar reads.
// ---------------------------------------------------------------------------
__global__ void __launch_bounds__(256, 1)
lstm_kernel(const void* __restrict__ seq_raw,
            const float* __restrict__ Whh0g, const float* __restrict__ Wih1g,
            const float* __restrict__ Whh1g,
            const float* __restrict__ bih1, const float* __restrict__ bhh1,
            const float* __restrict__ Wfc, const float* __restrict__ bfc,
            float* __restrict__ out) {
    extern __shared__ __align__(16) char smraw[];
    ulonglong2* W0v = (ulonglong2*)smraw;   // Whh0 [16 k4][256 g]  (64 KB)
    float* h0f = (float*)(W0v + 16 * 256);  // [2 buf][4 r][72]
    float* h1f = h0f + 576;                 // [2 buf][4 r][72]
    float* gts = h1f + 576;                 // [8 warp][2 set][8 j][stride 20]
    int*   idxs = (int*)(gts + 2560);       // [4 r][512 t]

    const int tid = threadIdx.x;
    const int brow0 = blockIdx.x * 4;

    const int lane = tid & 31;
    const int w    = tid >> 5;
    const int qq   = lane >> 3;        // gate quarter (i,f,g,o)
    const int jl   = lane & 7;
    const int g    = qq * 64 + w * 8 + jl;   // GEMV gate column
    const int ar   = qq;               // activation role: batch row
    const int aj   = w * 8 + jl;       // activation role: hidden unit

    // Repack Whh0 ([256 g][64 k] row-major global) -> smem [k4][g] ulonglong2.
    for (int i = tid; i < 16 * 256; i += 256) {
        int gg = i >> 4, k4 = i & 15;
        float4 w0 = *(const float4*)(Whh0g + (size_t)gg * Hh + k4 * 4);
        W0v[k4 * 256 + gg] = make_ulonglong2(pack2(w0.x, w0.y), pack2(w0.z, w0.w));
    }
    // Layer-1 weights for this thread's gate column -> registers (64 ull).
    ull wa[32], wb[32];
#pragma unroll
    for (int k2 = 0; k2 < 32; ++k2) {
        float2 a = *(const float2*)(Wih1g + (size_t)g * Hh + 2 * k2);
        float2 b = *(const float2*)(Whh1g + (size_t)g * Hh + 2 * k2);
        wa[k2] = pack2(a.x, a.y);
        wb[k2] = pack2(b.x, b.y);
    }
    // Indices for this CTA's 4 batch rows (dtype-adaptive)
    const int is64 = g_is64;
    for (int i = tid; i < 4 * Ss; i += 256) {
        int r = i >> 9, t = i & (Ss - 1);
        long long v;
        if (is64) v = ((const long long*)seq_raw)[(size_t)(brow0 + r) * Ss + t];
        else      v = (long long)((const int*)seq_raw)[(size_t)(brow0 + r) * Ss + t];
        idxs[r * Ss + t] = (int)v;
    }
    for (int i = tid; i < 1152; i += 256) h0f[i] = 0.f;  // zeros h0f+h1f (contiguous)
    const float bb = bih1[g] + bhh1[g];
    __syncthreads();

    float* gw1 = gts + w * 320;        // layer-1 gate exchange (160 floats)
    float* gw0 = gw1 + 160;            // layer-0(t+1) gate exchange
    const float* pT = g_projT;
    float c0 = 0.f, c1 = 0.f;

    // ---- prologue: layer-0 at t=0 has h0=0 -> gates are just the projections
    {
        float4 v;
        v.x = pT[(size_t)idxs[0 * Ss + 0] * Gg + g];
        v.y = pT[(size_t)idxs[1 * Ss + 0] * Gg + g];
        v.z = pT[(size_t)idxs[2 * Ss + 0] * Gg + g];
        v.w = pT[(size_t)idxs[3 * Ss + 0] * Gg + g];
        *(float4*)(gw0 + jl * 20 + qq * 4) = v;
        __syncwarp();
        float gi = gw0[jl * 20 + 0  + ar];
        float gf = gw0[jl * 20 + 4  + ar];
        float gG = gw0[jl * 20 + 8  + ar];
        float go = gw0[jl * 20 + 12 + ar];
        float iv = sigmf(gi), fv = sigmf(gf);
        float gv = tanhfast(gG), ov = sigmf(go);
        c0 = fv * c0 + iv * gv;
        h0f[/*buf0*/ ar * 72 + aj] = ov * tanhfast(c0);
        __syncthreads();  // h0[0] visible to all warps
    }

    // ---- main phases: ph handles layer1(t=ph) + layer0(t=ph+1), ONE barrier
#pragma unroll 1
    for (int ph = 0; ph < Ss - 1; ++ph) {
        const int p = ph & 1;
        const ulonglong2* yv = (const ulonglong2*)(h0f + p * 288);        // h0[ph]
        const ulonglong2* zv = (const ulonglong2*)(h1f + (p ^ 1) * 288);  // h1[ph-1]
        float* h0wr = h0f + (p ^ 1) * 288;  // h0[ph+1]
        float* h1wr = h1f + p * 288;        // h1[ph]

        // layer-0(ph+1) input projections from L2-resident table (early issue)
        float xv0 = pT[(size_t)idxs[0 * Ss + ph + 1] * Gg + g];
        float xv1 = pT[(size_t)idxs[1 * Ss + ph + 1] * Gg + g];
        float xv2 = pT[(size_t)idxs[2 * Ss + ph + 1] * Gg + g];
        float xv3 = pT[(size_t)idxs[3 * Ss + ph + 1] * Gg + g];

        // combined GEMV: a = y@Whh0^T (next layer-0), d = y@Wih1^T + z@Whh1^T
        // FULLY unrolled: wa/wb indices must be compile-time constants so the
        // arrays stay in registers.
        ull a0 = 0, a1 = 0, a2 = 0, a3 = 0;
        ull d0 = 0, d1 = 0, d2 = 0, d3 = 0;
#pragma unroll
        for (int k4 = 0; k4 < 16; ++k4) {
            ulonglong2 wv = W0v[k4 * 256 + g];
            ulonglong2 yA = yv[k4];
            ulonglong2 yB = yv[18 + k4];
            ulonglong2 yC = yv[36 + k4];
            ulonglong2 yD = yv[54 + k4];
            ulonglong2 zA = zv[k4];
            ulonglong2 zB = zv[18 + k4];
            ulonglong2 zC = zv[36 + k4];
            ulonglong2 zD = zv[54 + k4];
            a0 = ffma2(yA.x, wv.x, a0); a0 = ffma2(yA.y, wv.y, a0);
            a1 = ffma2(yB.x, wv.x, a1); a1 = ffma2(yB.y, wv.y, a1);
            a2 = ffma2(yC.x, wv.x, a2); a2 = ffma2(yC.y, wv.y, a2);
            a3 = ffma2(yD.x, wv.x, a3); a3 = ffma2(yD.y, wv.y, a3);
            d0 = ffma2(yA.x, wa[2 * k4], d0); d0 = ffma2(yA.y, wa[2 * k4 + 1], d0);
            d0 = ffma2(zA.x, wb[2 * k4], d0); d0 = ffma2(zA.y, wb[2 * k4 + 1], d0);
            d1 = ffma2(yB.x, wa[2 * k4], d1); d1 = ffma2(yB.y, wa[2 * k4 + 1], d1);
            d1 = ffma2(zB.x, wb[2 * k4], d1); d1 = ffma2(zB.y, wb[2 * k4 + 1], d1);
            d2 = ffma2(yC.x, wa[2 * k4], d2); d2 = ffma2(yC.y, wa[2 * k4 + 1], d2);
            d2 = ffma2(zC.x, wb[2 * k4], d2); d2 = ffma2(zC.y, wb[2 * k4 + 1], d2);
            d3 = ffma2(yD.x, wa[2 * k4], d3); d3 = ffma2(yD.y, wa[2 * k4 + 1], d3);
            d3 = ffma2(zD.x, wb[2 * k4], d3); d3 = ffma2(zD.y, wb[2 * k4 + 1], d3);
        }
        {
            float4 v1, v0n;
            v1.x = hsum2(d0) + bb;  v0n.x = hsum2(a0) + xv0;
            v1.y = hsum2(d1) + bb;  v0n.y = hsum2(a1) + xv1;
            v1.z = hsum2(d2) + bb;  v0n.z = hsum2(a2) + xv2;
            v1.w = hsum2(d3) + bb;  v0n.w = hsum2(a3) + xv3;
            *(float4*)(gw1 + jl * 20 + qq * 4) = v1;
            *(float4*)(gw0 + jl * 20 + qq * 4) = v0n;
        }
        __syncwarp();
        {   // act1(t=ph)
            float gi = gw1[jl * 20 + 0  + ar];
            float gf = gw1[jl * 20 + 4  + ar];
            float gG = gw1[jl * 20 + 8  + ar];
            float go = gw1[jl * 20 + 12 + ar];
            float iv = sigmf(gi), fv = sigmf(gf);
            float gv = tanhfast(gG), ov = sigmf(go);
            c1 = fv * c1 + iv * gv;
            h1wr[ar * 72 + aj] = ov * tanhfast(c1);
        }
        {   // act0(t=ph+1)
            float gi = gw0[jl * 20 + 0  + ar];
            float gf = gw0[jl * 20 + 4  + ar];
            float gG = gw0[jl * 20 + 8  + ar];
            float go = gw0[jl * 20 + 12 + ar];
            float iv = sigmf(gi), fv = sigmf(gf);
            float gv = tanhfast(gG), ov = sigmf(go);
            c0 = fv * c0 + iv * gv;
            h0wr[ar * 72 + aj] = ov * tanhfast(c0);
        }
        __syncthreads();  // single barrier per phase
    }

    // ---- epilogue: layer-1 at t = Ss-1 = 511
    {
        const int p = (Ss - 1) & 1;  // 1
        const ulonglong2* yv = (const ulonglong2*)(h0f + p * 288);        // h0[511]
        const ulonglong2* zv = (const ulonglong2*)(h1f + (p ^ 1) * 288);  // h1[510]
        ull d0 = 0, d1 = 0, d2 = 0, d3 = 0;
#pragma unroll
        for (int k4 = 0; k4 < 16; ++k4) {
            ulonglong2 yA = yv[k4],      yB = yv[18 + k4];
            ulonglong2 yC = yv[36 + k4], yD = yv[54 + k4];
            ulonglong2 zA = zv[k4],      zB = zv[18 + k4];
            ulonglong2 zC = zv[36 + k4], zD = zv[54 + k4];
            d0 = ffma2(yA.x, wa[2 * k4], d0); d0 = ffma2(yA.y, wa[2 * k4 + 1], d0);
            d0 = ffma2(zA.x, wb[2 * k4], d0); d0 = ffma2(zA.y, wb[2 * k4 + 1], d0);
            d1 = ffma2(yB.x, wa[2 * k4], d1); d1 = ffma2(yB.y, wa[2 * k4 + 1], d1);
            d1 = ffma2(zB.x, wb[2 * k4], d1); d1 = ffma2(zB.y, wb[2 * k4 + 1], d1);
            d2 = ffma2(yC.x, wa[2 * k4], d2); d2 = ffma2(yC.y, wa[2 * k4 + 1], d2);
            d2 = ffma2(zC.x, wb[2 * k4], d2); d2 = ffma2(zC.y, wb[2 * k4 + 1], d2);
            d3 = ffma2(yD.x, wa[2 * k4], d3); d3 = ffma2(yD.y, wa[2 * k4 + 1], d3);
            d3 = ffma2(zD.x, wb[2 * k4], d3); d3 = ffma2(zD.y, wb[2 * k4 + 1], d3);
        }
        {
            float4 v1;
            v1.x = hsum2(d0) + bb;
            v1.y = hsum2(d1) + bb;
            v1.z = hsum2(d2) + bb;
            v1.w = hsum2(d3) + bb;
            *(float4*)(gw1 + jl * 20 + qq * 4) = v1;
        }
        __syncwarp();
        {
            float gi = gw1[jl * 20 + 0  + ar];
            float gf = gw1[jl * 20 + 4  + ar];
            float gG = gw1[jl * 20 + 8  + ar];
            float go = gw1[jl * 20 + 12 + ar];
            float iv = sigmf(gi), fv = sigmf(gf);
            float gv = tanhfast(gG), ov = sigmf(go);
            c1 = fv * c1 + iv * gv;
            h1f[p * 288 + ar * 72 + aj] = ov * tanhfast(c1);  // h1[511] -> buf1
        }
        __syncthreads();
    }

    // ---- final FC: out = sigmoid(h1_T @ Wfc^T + bfc), shape [B, 2] ----
    if (tid < 8) {
        const float* hfin = h1f + ((Ss - 1) & 1) * 288;
        int r = tid >> 1, o = tid & 1;
        float s = bfc[o];
#pragma unroll
        for (int j = 0; j < 64; ++j) s += hfin[r * 72 + j] * Wfc[o * 64 + j];
        out[(size_t)(brow0 + r) * 2 + o] = sigmf(s);
    }
}

// ---------------------------------------------------------------------------
extern "C" void kernel_launch(void* const* d_in, const int* in_sizes, int n_in,
                              void* d_out, int out_size) {
    const void*  seq  = d_in[0];
    const float* emb  = (const float*)d_in[1];
    const float* Wih0 = (const float*)d_in[2];
    const float* Whh0 = (const float*)d_in[3];
    const float* bih0 = (const float*)d_in[4];
    const float* bhh0 = (const float*)d_in[5];
    const float* Wih1 = (const float*)d_in[6];
    const float* Whh1 = (const float*)d_in[7];
    const float* bih1 = (const float*)d_in[8];
    const float* bhh1 = (const float*)d_in[9];
    const float* Wfc  = (const float*)d_in[10];
    const float* bfc  = (const float*)d_in[11];
    float* out = (float*)d_out;

    const int projSmem = (64 * 256 + 64 * 32) * 8;                           // 147456
    const int lstmSmem = 16 * 256 * 16 + (576 + 576 + 2560) * 4 + 4 * Ss * 4;  // 88576

    cudaFuncSetAttribute(proj_kernel, cudaFuncAttributeMaxDynamicSharedMemorySize, projSmem);
    cudaFuncSetAttribute(lstm_kernel, cudaFuncAttributeMaxDynamicSharedMemorySize, lstmSmem);

    proj_kernel<<<(Vv + 31) / 32, 256, projSmem>>>(emb, Wih0, bih0, bhh0, seq);
    lstm_kernel<<<Bb / 4, 256, lstmSmem>>>(seq, Whh0, Wih1, Whh1,
                                           bih1, bhh1, Wfc, bfc, out);
}